// round 4
// baseline (speedup 1.0000x reference)
#include <cuda_runtime.h>

#define NA 8192
#define NN 65536
#define NE 262144
#define DD 128
#define GN_EPS 1e-5f
#define TILE 64
#define AST 132      // activation row stride (floats)
#define CST 132      // gemm-output row stride
#define INST 388     // ctx0-input row stride (3*128 padded)
#define NTH 512
#define WCH 32       // k-chunk width
#define SWBUF (WCH * 128)

// scratch (device globals: allocation-free rule)
__device__ __align__(16) float g_q[NA * DD];
__device__ __align__(16) float g_a[NA * DD];
__device__ __align__(16) float g_actors[NA * DD];

// ---------- packed f32x2 helpers ----------
__device__ __forceinline__ void ffma2(unsigned long long& acc, unsigned long long w,
                                      unsigned long long a) {
    asm volatile("fma.rn.f32x2 %0, %1, %2, %0;" : "+l"(acc) : "l"(w), "l"(a));
}
__device__ __forceinline__ unsigned long long pack2(float x) {
    unsigned long long r;
    asm("mov.b64 %0, {%1, %1};" : "=l"(r) : "f"(x));
    return r;
}
__device__ __forceinline__ float2 unpack2(unsigned long long v) {
    float2 r;
    asm("mov.b64 {%0, %1}, %2;" : "=f"(r.x), "=f"(r.y) : "l"(v));
    return r;
}

// ---------- CTA-tiled GEMM:  C[64][128] = Act[64][K] * W[128][K]^T ----------
// 512 threads: toc = t&31 (4 output channels as 2 f32x2 pairs), teg = t>>5 (4 edges).
// Weights staged k-major in double-buffered smem, 32-wide k chunks, ONE barrier
// per chunk (STS -> sync -> prefetch next chunk -> compute current).
__device__ void cta_gemm(const float* __restrict__ W, int K,
                         const float* sAct, int actStride,
                         float* sC, float* sW, int t) {
    const int toc = t & 31;
    const int teg = t >> 5;  // 0..15
    unsigned long long acc[4][2];
#pragma unroll
    for (int i = 0; i < 4; i++) { acc[i][0] = 0ull; acc[i][1] = 0ull; }

    // oc-major lane mapping -> conflict-free STS; global reads hit L2 (weights hot)
    const int wo = t & 127;       // output channel
    const int wk0 = (t >> 7) * 4; // k offset within chunk, r=0 (0,4,8,12)
    const int wk1 = wk0 + 16;     // r=1 (16,20,24,28)
    const int nchunk = K >> 5;

    float4 wreg[2];
    wreg[0] = *(const float4*)(W + wo * K + wk0);
    wreg[1] = *(const float4*)(W + wo * K + wk1);

    for (int c = 0; c < nchunk; c++) {
        float* sWb = sW + (c & 1) * SWBUF;
        // stage chunk c (safe: readers of this buffer finished before last sync)
        sWb[(wk0 + 0) * 128 + wo] = wreg[0].x;
        sWb[(wk0 + 1) * 128 + wo] = wreg[0].y;
        sWb[(wk0 + 2) * 128 + wo] = wreg[0].z;
        sWb[(wk0 + 3) * 128 + wo] = wreg[0].w;
        sWb[(wk1 + 0) * 128 + wo] = wreg[1].x;
        sWb[(wk1 + 1) * 128 + wo] = wreg[1].y;
        sWb[(wk1 + 2) * 128 + wo] = wreg[1].z;
        sWb[(wk1 + 3) * 128 + wo] = wreg[1].w;
        __syncthreads();
        if (c + 1 < nchunk) {  // prefetch next chunk; latency overlaps compute
            const int k0n = (c + 1) << 5;
            wreg[0] = *(const float4*)(W + wo * K + k0n + wk0);
            wreg[1] = *(const float4*)(W + wo * K + k0n + wk1);
        }
        const int k0 = c << 5;
#pragma unroll
        for (int kq = 0; kq < 8; kq++) {
            float a[4][4];
#pragma unroll
            for (int i = 0; i < 4; i++)  // broadcast loads (whole warp shares teg)
                *(float4*)(&a[i][0]) =
                    *(const float4*)(sAct + (teg * 4 + i) * actStride + k0 + kq * 4);
#pragma unroll
            for (int j = 0; j < 4; j++) {
                const ulonglong2 w2 = *(const ulonglong2*)(sWb + (kq * 4 + j) * 128 + toc * 4);
#pragma unroll
                for (int i = 0; i < 4; i++) {
                    unsigned long long aa = pack2(a[i][j]);
                    ffma2(acc[i][0], w2.x, aa);
                    ffma2(acc[i][1], w2.y, aa);
                }
            }
        }
    }
#pragma unroll
    for (int i = 0; i < 4; i++) {
        float2 p0 = unpack2(acc[i][0]);
        float2 p1 = unpack2(acc[i][1]);
        *(float4*)(sC + (teg * 4 + i) * CST + toc * 4) = make_float4(p0.x, p0.y, p1.x, p1.y);
    }
}

// ---------- per-row GroupNorm(1 group) over 128 channels, warp per row ----------
__device__ void cta_gn(const float* sC, float* dst, int dstStride,
                       const float* __restrict__ gamma, const float* __restrict__ beta,
                       bool relu, int t) {
    const int warp = t >> 5, lane = t & 31;
    float gg[4], bb[4];
#pragma unroll
    for (int j = 0; j < 4; j++) { gg[j] = gamma[lane + 32 * j]; bb[j] = beta[lane + 32 * j]; }
    for (int e = warp; e < TILE; e += 16) {
        const float* row = sC + e * CST;
        float v[4], s = 0.f, s2 = 0.f;
#pragma unroll
        for (int j = 0; j < 4; j++) {
            v[j] = row[lane + 32 * j];
            s += v[j];
            s2 += v[j] * v[j];
        }
#pragma unroll
        for (int o = 16; o > 0; o >>= 1) {
            s += __shfl_xor_sync(0xffffffffu, s, o);
            s2 += __shfl_xor_sync(0xffffffffu, s2, o);
        }
        float mu = s * (1.f / 128.f);
        float var = s2 * (1.f / 128.f) - mu * mu;
        float rstd = rsqrtf(var + GN_EPS);
#pragma unroll
        for (int j = 0; j < 4; j++) {
            float y = (v[j] - mu) * rstd * gg[j] + bb[j];
            if (relu) y = fmaxf(y, 0.f);
            dst[e * dstStride + lane + 32 * j] = y;
        }
    }
}

// ---------- actor pre: q = relu(gn(actors@qW^T)), a = actors@agtW^T ----------
__global__ void __launch_bounds__(NTH, 1)
pre_kernel(const float* __restrict__ actors_in, const float* __restrict__ qW,
           const float* __restrict__ qg, const float* __restrict__ qb,
           const float* __restrict__ aW, int blk) {
    extern __shared__ float sm[];
    float* sA = sm;
    float* sC = sA + TILE * AST;
    float* sW = sC + TILE * CST;
    const float* cur = blk ? g_actors : actors_in;
    const int t = threadIdx.x;
    const int r0 = blockIdx.x * TILE;
    for (int idx = t; idx < TILE * 32; idx += NTH) {
        int e = idx >> 5, c4 = idx & 31;
        *(float4*)(sA + e * AST + c4 * 4) =
            *(const float4*)(cur + (size_t)(r0 + e) * DD + c4 * 4);
    }
    __syncthreads();
    cta_gemm(qW, DD, sA, AST, sC, sW, t);
    __syncthreads();
    cta_gn(sC, g_q + (size_t)r0 * DD, DD, qg, qb, true, t);
    __syncthreads();
    cta_gemm(aW, DD, sA, AST, sC, sW, t);
    __syncthreads();
    for (int idx = t; idx < TILE * 32; idx += NTH) {
        int e = idx >> 5, c4 = idx & 31;
        *(float4*)(g_a + (size_t)(r0 + e) * DD + c4 * 4) = *(const float4*)(sC + e * CST + c4 * 4);
    }
}

// ---------- fused edge pipeline ----------
__global__ void __launch_bounds__(NTH, 1)
edge_kernel(const float* __restrict__ actor_ctrs, const float* __restrict__ node_ctrs,
            const int* __restrict__ hi, const int* __restrict__ wi,
            const float* __restrict__ nodes,
            const float* __restrict__ d0W, const float* __restrict__ d0b,
            const float* __restrict__ d1W, const float* __restrict__ d1g,
            const float* __restrict__ d1b,
            const float* __restrict__ c0W, const float* __restrict__ c0g,
            const float* __restrict__ c0b, const float* __restrict__ c1W) {
    extern __shared__ float sm[];
    float* sIn = sm;                    // [64][388] : [d | q | c]
    float* sA = sIn + TILE * INST;      // [64][132]
    float* sC = sA + TILE * AST;        // [64][132]
    float* sW = sC + TILE * CST;        // 2 x [32][128]
    int* shi = (int*)(sW + 2 * SWBUF);
    int* swi = shi + TILE;
    float* sdx = (float*)(swi + TILE);
    float* sdy = sdx + TILE;

    const int t = threadIdx.x;
    const int e0 = blockIdx.x * TILE;
    if (t < TILE) {
        int h = hi[e0 + t], w = wi[e0 + t];
        shi[t] = h;
        swi[t] = w;
        sdx[t] = actor_ctrs[2 * h] - node_ctrs[2 * w];
        sdy[t] = actor_ctrs[2 * h + 1] - node_ctrs[2 * w + 1];
    }
    __syncthreads();
    // H1 = relu(dist0(dvec))
    for (int idx = t; idx < TILE * DD; idx += NTH) {
        int e = idx >> 7, ch = idx & 127;
        float v = fmaf(d0W[2 * ch], sdx[e], fmaf(d0W[2 * ch + 1], sdy[e], d0b[ch]));
        sA[e * AST + ch] = fmaxf(v, 0.f);
    }
    // gather q[hi] and nodes[wi] into sIn cols [128:384)
    for (int idx = t; idx < TILE * 32; idx += NTH) {
        int e = idx >> 5, c4 = idx & 31;
        *(float4*)(sIn + e * INST + DD + c4 * 4) =
            *(const float4*)(g_q + (size_t)shi[e] * DD + c4 * 4);
        *(float4*)(sIn + e * INST + 2 * DD + c4 * 4) =
            *(const float4*)(nodes + (size_t)swi[e] * DD + c4 * 4);
    }
    __syncthreads();
    cta_gemm(d1W, DD, sA, AST, sC, sW, t);      // H1 @ dist1^T
    __syncthreads();
    cta_gn(sC, sIn, INST, d1g, d1b, true, t);   // -> sIn[:,0:128]
    __syncthreads();
    cta_gemm(c0W, 3 * DD, sIn, INST, sC, sW, t);  // [d,q,c] @ ctx0^T
    __syncthreads();
    cta_gn(sC, sA, AST, c0g, c0b, true, t);
    __syncthreads();
    cta_gemm(c1W, DD, sA, AST, sC, sW, t);      // @ ctx1^T
    __syncthreads();
    // vectorized scatter-add into g_a (red.v4: 4x fewer L2 red ops)
    for (int idx = t; idx < TILE * 32; idx += NTH) {
        int e = idx >> 5, c4 = idx & 31;
        const float4 v = *(const float4*)(sC + e * CST + c4 * 4);
        const float* p = g_a + (size_t)shi[e] * DD + c4 * 4;
        asm volatile("red.global.add.v4.f32 [%0], {%1, %2, %3, %4};"
                     :: "l"(p), "f"(v.x), "f"(v.y), "f"(v.z), "f"(v.w)
                     : "memory");
    }
}

// ---------- actor post: a=relu(gn(a)); a=gn(a@linW^T); out=relu(a+res) ----------
__global__ void __launch_bounds__(NTH, 1)
post_kernel(const float* __restrict__ actors_in, const float* __restrict__ ng,
            const float* __restrict__ nb, const float* __restrict__ lW,
            const float* __restrict__ lg, const float* __restrict__ lb,
            float* __restrict__ out, int blk) {
    extern __shared__ float sm[];
    float* sA = sm;
    float* sC = sA + TILE * AST;
    float* sW = sC + TILE * CST;
    const float* cur = blk ? g_actors : actors_in;
    float* nxt = blk ? out : g_actors;
    const int t = threadIdx.x;
    const int r0 = blockIdx.x * TILE;
    for (int idx = t; idx < TILE * 32; idx += NTH) {
        int e = idx >> 5, c4 = idx & 31;
        *(float4*)(sC + e * CST + c4 * 4) = *(const float4*)(g_a + (size_t)(r0 + e) * DD + c4 * 4);
    }
    __syncthreads();
    cta_gn(sC, sA, AST, ng, nb, true, t);
    __syncthreads();
    cta_gemm(lW, DD, sA, AST, sC, sW, t);
    __syncthreads();
    cta_gn(sC, sA, AST, lg, lb, false, t);
    __syncthreads();
    for (int idx = t; idx < TILE * 32; idx += NTH) {
        int e = idx >> 5, c4 = idx & 31;
        float4 v = *(const float4*)(sA + e * AST + c4 * 4);
        float4 r = *(const float4*)(cur + (size_t)(r0 + e) * DD + c4 * 4);
        float4 o;
        o.x = fmaxf(v.x + r.x, 0.f);
        o.y = fmaxf(v.y + r.y, 0.f);
        o.z = fmaxf(v.z + r.z, 0.f);
        o.w = fmaxf(v.w + r.w, 0.f);
        *(float4*)(nxt + (size_t)(r0 + e) * DD + c4 * 4) = o;
    }
}

#define SMEM_ACT ((TILE * AST + TILE * CST + 2 * SWBUF) * 4)
#define SMEM_EDGE ((TILE * INST + TILE * AST + TILE * CST + 2 * SWBUF) * 4 + TILE * 4 * 4)

extern "C" void kernel_launch(void* const* d_in, const int* in_sizes, int n_in,
                              void* d_out, int out_size) {
    (void)in_sizes; (void)n_in; (void)out_size;
    const float* actors = (const float*)d_in[0];
    const float* nodes = (const float*)d_in[1];
    const float* actor_ctrs = (const float*)d_in[2];
    const float* node_ctrs = (const float*)d_in[3];
    const int* hi = (const int*)d_in[4];
    const int* wi = (const int*)d_in[5];
    const float* d0W = (const float*)d_in[6];
    const float* d0b = (const float*)d_in[7];
    const float* d1W = (const float*)d_in[8];
    const float* d1g = (const float*)d_in[9];
    const float* d1b = (const float*)d_in[10];
    const float* qW = (const float*)d_in[11];
    const float* qg = (const float*)d_in[12];
    const float* qb = (const float*)d_in[13];
    const float* c0W = (const float*)d_in[14];
    const float* c0g = (const float*)d_in[15];
    const float* c0b = (const float*)d_in[16];
    const float* c1W = (const float*)d_in[17];
    const float* aW = (const float*)d_in[18];
    const float* ng = (const float*)d_in[19];
    const float* nb = (const float*)d_in[20];
    const float* lW = (const float*)d_in[21];
    const float* lg = (const float*)d_in[22];
    const float* lb = (const float*)d_in[23];
    float* out = (float*)d_out;

    cudaFuncSetAttribute(pre_kernel, cudaFuncAttributeMaxDynamicSharedMemorySize, SMEM_ACT);
    cudaFuncSetAttribute(edge_kernel, cudaFuncAttributeMaxDynamicSharedMemorySize, SMEM_EDGE);
    cudaFuncSetAttribute(post_kernel, cudaFuncAttributeMaxDynamicSharedMemorySize, SMEM_ACT);

    for (int blk = 0; blk < 2; blk++) {
        const int off = blk * DD;
        pre_kernel<<<NA / TILE, NTH, SMEM_ACT>>>(actors, qW + blk * DD * DD, qg + off, qb + off,
                                                 aW + blk * DD * DD, blk);
        edge_kernel<<<NE / TILE, NTH, SMEM_EDGE>>>(
            actor_ctrs, node_ctrs, hi, wi, nodes,
            d0W + blk * DD * 2, d0b + off,
            d1W + blk * DD * DD, d1g + off, d1b + off,
            c0W + blk * DD * 3 * DD, c0g + off, c0b + off,
            c1W + blk * DD * DD);
        post_kernel<<<NA / TILE, NTH, SMEM_ACT>>>(actors, ng + off, nb + off, lW + blk * DD * DD,
                                                  lg + off, lb + off, out, blk);
    }
}

// round 5
// speedup vs baseline: 1.1076x; 1.1076x over previous
#include <cuda_runtime.h>

#define NA 8192
#define NN 65536
#define NE 262144
#define DD 128
#define GN_EPS 1e-5f
#define TILE 128
#define STR 132      // activation row stride (floats)
#define NTH 256
#define WCH 16       // weight k-chunk width
#define SWBUF (WCH * 128)

// scratch (device globals: allocation-free rule)
__device__ __align__(16) float g_q[NA * DD];
__device__ __align__(16) float g_a[NA * DD];
__device__ __align__(16) float g_actors[NA * DD];

// ---------- packed f32x2 helpers ----------
__device__ __forceinline__ void ffma2(unsigned long long& acc, unsigned long long w,
                                      unsigned long long a) {
    asm volatile("fma.rn.f32x2 %0, %1, %2, %0;" : "+l"(acc) : "l"(w), "l"(a));
}
__device__ __forceinline__ unsigned long long pack2(float x) {
    unsigned long long r;
    asm("mov.b64 %0, {%1, %1};" : "=l"(r) : "f"(x));
    return r;
}
__device__ __forceinline__ float2 unpack2(unsigned long long v) {
    float2 r;
    asm("mov.b64 {%0, %1}, %2;" : "=f"(r.x), "=f"(r.y) : "l"(v));
    return r;
}
__device__ __forceinline__ void redv4(const float* p, float a, float b, float c, float d) {
    asm volatile("red.global.add.v4.f32 [%0], {%1, %2, %3, %4};"
                 :: "l"(p), "f"(a), "f"(b), "f"(c), "f"(d) : "memory");
}

// thread tile geometry: 8 warps = 4 edge-blocks x 2 oc-blocks
// lane = eg*8 + og ; thread owns edges [eRow0, eRow0+8), ocs [o0, o0+8)
struct TG {
    int t, lane, og, ocblk, eRow0, o0;
};
__device__ __forceinline__ TG tgeom() {
    TG g;
    g.t = threadIdx.x;
    const int warp = g.t >> 5;
    g.lane = g.t & 31;
    g.og = g.lane & 7;
    g.ocblk = warp & 1;
    g.eRow0 = (warp >> 1) * 32 + (g.lane >> 3) * 8;
    g.o0 = g.ocblk * 64 + g.og * 8;
    return g;
}

// ---------- 8x8 register-tile GEMM: acc += Act[128][K] * W[128][K]^T ----------
// Weights double-buffered in smem (k-major, 16-wide chunks, 1 barrier/chunk).
__device__ __forceinline__ void gemm8x8(const float* __restrict__ W, int ldW, int K,
                                        const float* sAct, float* sW,
                                        unsigned long long (&acc)[8][4], const TG& g) {
    const int oc = g.t & 127;
    const int kh = (g.t >> 7) * 8;
    const int nch = K >> 4;
    float4 w0 = *(const float4*)(W + oc * ldW + kh);
    float4 w1 = *(const float4*)(W + oc * ldW + kh + 4);
    for (int c = 0; c < nch; c++) {
        float* sb = sW + (c & 1) * SWBUF;
        sb[(kh + 0) * 128 + oc] = w0.x;
        sb[(kh + 1) * 128 + oc] = w0.y;
        sb[(kh + 2) * 128 + oc] = w0.z;
        sb[(kh + 3) * 128 + oc] = w0.w;
        sb[(kh + 4) * 128 + oc] = w1.x;
        sb[(kh + 5) * 128 + oc] = w1.y;
        sb[(kh + 6) * 128 + oc] = w1.z;
        sb[(kh + 7) * 128 + oc] = w1.w;
        __syncthreads();
        if (c + 1 < nch) {
            const float* Wp = W + oc * ldW + ((c + 1) << 4) + kh;
            w0 = *(const float4*)(Wp);
            w1 = *(const float4*)(Wp + 4);
        }
        const int k0 = c << 4;
#pragma unroll
        for (int kq = 0; kq < 4; kq++) {
            float4 a4[8];
#pragma unroll
            for (int i = 0; i < 8; i++)  // 8-way broadcast within warp
                a4[i] = *(const float4*)(sAct + (g.eRow0 + i) * STR + k0 + kq * 4);
#pragma unroll
            for (int kk = 0; kk < 4; kk++) {
                const int k = kq * 4 + kk;
                const ulonglong2 wa = *(const ulonglong2*)(sb + k * 128 + g.o0);
                const ulonglong2 wb = *(const ulonglong2*)(sb + k * 128 + g.o0 + 4);
#pragma unroll
                for (int i = 0; i < 8; i++) {
                    const float av = (kk == 0) ? a4[i].x : (kk == 1) ? a4[i].y
                                   : (kk == 2) ? a4[i].z : a4[i].w;
                    const unsigned long long aa = pack2(av);
                    ffma2(acc[i][0], wa.x, aa);
                    ffma2(acc[i][1], wa.y, aa);
                    ffma2(acc[i][2], wb.x, aa);
                    ffma2(acc[i][3], wb.y, aa);
                }
            }
        }
    }
}

// ---------- GroupNorm(1 group, 128 ch) from accumulator registers ----------
// MODE 0: store y    MODE 1: store relu(y)    MODE 2: store relu(y + res)
template <int MODE>
__device__ __forceinline__ void gn_regs(const unsigned long long (&acc)[8][4],
                                        float* dst, int dstStride,
                                        const float* __restrict__ gamma,
                                        const float* __restrict__ beta,
                                        float* sRed, const TG& g,
                                        const float* res /*stride 128*/) {
    const float4 g0 = *(const float4*)(gamma + g.o0);
    const float4 g1 = *(const float4*)(gamma + g.o0 + 4);
    const float4 b0 = *(const float4*)(beta + g.o0);
    const float4 b1 = *(const float4*)(beta + g.o0 + 4);
#pragma unroll
    for (int i = 0; i < 8; i++) {
        float s = 0.f, s2 = 0.f;
#pragma unroll
        for (int j = 0; j < 4; j++) {
            float2 p = unpack2(acc[i][j]);
            s += p.x + p.y;
            s2 += p.x * p.x + p.y * p.y;
        }
#pragma unroll
        for (int o = 4; o > 0; o >>= 1) {  // reduce over 8 oc-lanes
            s += __shfl_xor_sync(0xffffffffu, s, o);
            s2 += __shfl_xor_sync(0xffffffffu, s2, o);
        }
        if (g.og == 0) {
            sRed[(g.eRow0 + i) * 4 + g.ocblk * 2 + 0] = s;
            sRed[(g.eRow0 + i) * 4 + g.ocblk * 2 + 1] = s2;
        }
    }
    __syncthreads();
#pragma unroll
    for (int i = 0; i < 8; i++) {
        const int e = g.eRow0 + i;
        const float s = sRed[e * 4 + 0] + sRed[e * 4 + 2];
        const float s2 = sRed[e * 4 + 1] + sRed[e * 4 + 3];
        const float mu = s * (1.f / 128.f);
        const float var = s2 * (1.f / 128.f) - mu * mu;
        const float rstd = rsqrtf(var + GN_EPS);
        float v[8];
#pragma unroll
        for (int j = 0; j < 4; j++) {
            float2 p = unpack2(acc[i][j]);
            v[2 * j] = p.x;
            v[2 * j + 1] = p.y;
        }
        float y[8];
        y[0] = (v[0] - mu) * rstd * g0.x + b0.x;
        y[1] = (v[1] - mu) * rstd * g0.y + b0.y;
        y[2] = (v[2] - mu) * rstd * g0.z + b0.z;
        y[3] = (v[3] - mu) * rstd * g0.w + b0.w;
        y[4] = (v[4] - mu) * rstd * g1.x + b1.x;
        y[5] = (v[5] - mu) * rstd * g1.y + b1.y;
        y[6] = (v[6] - mu) * rstd * g1.z + b1.z;
        y[7] = (v[7] - mu) * rstd * g1.w + b1.w;
        if (MODE == 2) {
            const float4 r0 = *(const float4*)(res + (size_t)e * DD + g.o0);
            const float4 r1 = *(const float4*)(res + (size_t)e * DD + g.o0 + 4);
            y[0] += r0.x; y[1] += r0.y; y[2] += r0.z; y[3] += r0.w;
            y[4] += r1.x; y[5] += r1.y; y[6] += r1.z; y[7] += r1.w;
        }
        if (MODE >= 1) {
#pragma unroll
            for (int j = 0; j < 8; j++) y[j] = fmaxf(y[j], 0.f);
        }
        *(float4*)(dst + (size_t)e * dstStride + g.o0) = make_float4(y[0], y[1], y[2], y[3]);
        *(float4*)(dst + (size_t)e * dstStride + g.o0 + 4) = make_float4(y[4], y[5], y[6], y[7]);
    }
}

#define ZACC(acc)                                          \
    _Pragma("unroll") for (int _i = 0; _i < 8; _i++)       \
        _Pragma("unroll") for (int _j = 0; _j < 4; _j++)   \
            acc[_i][_j] = 0ull;

// ---------- actor pre: q = relu(gn(actors@qW^T)), a = actors@agtW^T ----------
__global__ void __launch_bounds__(NTH, 1)
pre_kernel(const float* __restrict__ actors_in, const float* __restrict__ qW,
           const float* __restrict__ qg, const float* __restrict__ qb,
           const float* __restrict__ aW, int blk) {
    extern __shared__ float sm[];
    float* sA = sm;                  // [128][132]
    float* sW = sA + TILE * STR;     // 2 x [16][128]
    float* sRed = sW + 2 * SWBUF;    // [128][4]
    const float* cur = blk ? g_actors : actors_in;
    const TG g = tgeom();
    const int t = g.t;
    const int r0 = blockIdx.x * TILE;
    for (int idx = t; idx < TILE * 32; idx += NTH) {
        int e = idx >> 5, c4 = idx & 31;
        *(float4*)(sA + e * STR + c4 * 4) =
            *(const float4*)(cur + (size_t)(r0 + e) * DD + c4 * 4);
    }
    __syncthreads();
    unsigned long long acc[8][4];
    ZACC(acc);
    gemm8x8(qW, DD, DD, sA, sW, acc, g);
    __syncthreads();
    gn_regs<1>(acc, g_q + (size_t)r0 * DD, DD, qg, qb, sRed, g, nullptr);
    ZACC(acc);
    gemm8x8(aW, DD, DD, sA, sW, acc, g);
#pragma unroll
    for (int i = 0; i < 8; i++) {
        float v[8];
#pragma unroll
        for (int j = 0; j < 4; j++) {
            float2 p = unpack2(acc[i][j]);
            v[2 * j] = p.x;
            v[2 * j + 1] = p.y;
        }
        float* dst = g_a + (size_t)(r0 + g.eRow0 + i) * DD + g.o0;
        *(float4*)(dst) = make_float4(v[0], v[1], v[2], v[3]);
        *(float4*)(dst + 4) = make_float4(v[4], v[5], v[6], v[7]);
    }
}

// ---------- fused edge pipeline ----------
__global__ void __launch_bounds__(NTH, 1)
edge_kernel(const float* __restrict__ actor_ctrs, const float* __restrict__ node_ctrs,
            const int* __restrict__ hi, const int* __restrict__ wi,
            const float* __restrict__ nodes,
            const float* __restrict__ d0W, const float* __restrict__ d0b,
            const float* __restrict__ d1W, const float* __restrict__ d1g,
            const float* __restrict__ d1b,
            const float* __restrict__ c0W, const float* __restrict__ c0g,
            const float* __restrict__ c0b, const float* __restrict__ c1W) {
    extern __shared__ float sm[];
    float* sD = sm;                   // [128][132]: H1, then gn(dist1 out), then gn(ctx0 out)
    float* sQ = sD + TILE * STR;      // [128][132]
    float* sC = sQ + TILE * STR;      // [128][132]
    float* sW = sC + TILE * STR;      // 2 x [16][128]
    float* sRed = sW + 2 * SWBUF;     // [128][4]
    int* shi = (int*)(sRed + TILE * 4);
    int* swi = shi + TILE;
    float* sdx = (float*)(swi + TILE);
    float* sdy = sdx + TILE;

    const TG g = tgeom();
    const int t = g.t;
    const int e0 = blockIdx.x * TILE;
    if (t < TILE) {
        int h = hi[e0 + t], w = wi[e0 + t];
        shi[t] = h;
        swi[t] = w;
        sdx[t] = actor_ctrs[2 * h] - node_ctrs[2 * w];
        sdy[t] = actor_ctrs[2 * h + 1] - node_ctrs[2 * w + 1];
    }
    __syncthreads();
    // H1 = relu(dist0(dvec)) -> sD
    for (int idx = t; idx < TILE * DD; idx += NTH) {
        int e = idx >> 7, ch = idx & 127;
        float v = fmaf(d0W[2 * ch], sdx[e], fmaf(d0W[2 * ch + 1], sdy[e], d0b[ch]));
        sD[e * STR + ch] = fmaxf(v, 0.f);
    }
    // gather q[hi] -> sQ, nodes[wi] -> sC
    for (int idx = t; idx < TILE * 32; idx += NTH) {
        int e = idx >> 5, c4 = idx & 31;
        *(float4*)(sQ + e * STR + c4 * 4) = *(const float4*)(g_q + (size_t)shi[e] * DD + c4 * 4);
        *(float4*)(sC + e * STR + c4 * 4) = *(const float4*)(nodes + (size_t)swi[e] * DD + c4 * 4);
    }
    __syncthreads();

    unsigned long long acc[8][4];
    // d = relu(gn(H1 @ dist1^T)) -> sD (in place via regs)
    ZACC(acc);
    gemm8x8(d1W, DD, DD, sD, sW, acc, g);
    __syncthreads();
    gn_regs<1>(acc, sD, STR, d1g, d1b, sRed, g, nullptr);
    __syncthreads();
    // m = relu(gn([d,q,c] @ ctx0^T)) : 3 accumulating K=128 GEMMs -> sD
    ZACC(acc);
    gemm8x8(c0W, 3 * DD, DD, sD, sW, acc, g);
    gemm8x8(c0W + DD, 3 * DD, DD, sQ, sW, acc, g);
    gemm8x8(c0W + 2 * DD, 3 * DD, DD, sC, sW, acc, g);
    __syncthreads();
    gn_regs<1>(acc, sD, STR, c0g, c0b, sRed, g, nullptr);
    __syncthreads();
    // m @ ctx1^T -> scatter-add straight from registers
    ZACC(acc);
    gemm8x8(c1W, DD, DD, sD, sW, acc, g);
#pragma unroll
    for (int i = 0; i < 8; i++) {
        float v[8];
#pragma unroll
        for (int j = 0; j < 4; j++) {
            float2 p = unpack2(acc[i][j]);
            v[2 * j] = p.x;
            v[2 * j + 1] = p.y;
        }
        const float* p = g_a + (size_t)shi[g.eRow0 + i] * DD + g.o0;
        redv4(p, v[0], v[1], v[2], v[3]);
        redv4(p + 4, v[4], v[5], v[6], v[7]);
    }
}

// ---------- actor post: a=relu(gn(a)); a=gn(a@linW^T); out=relu(a+res) ----------
__global__ void __launch_bounds__(NTH, 1)
post_kernel(const float* __restrict__ actors_in, const float* __restrict__ ng,
            const float* __restrict__ nb, const float* __restrict__ lW,
            const float* __restrict__ lg, const float* __restrict__ lb,
            float* __restrict__ out, int blk) {
    extern __shared__ float sm[];
    float* sA = sm;                  // [128][132]
    float* sW = sA + TILE * STR;
    float* sRed = sW + 2 * SWBUF;
    const float* cur = blk ? g_actors : actors_in;
    float* nxt = blk ? out : g_actors;
    const TG g = tgeom();
    const int t = g.t;
    const int r0 = blockIdx.x * TILE;
    // relu(gn(g_a)) -> sA  (warp per row, stats over 128 ch)
    {
        const int warp = t >> 5, lane = t & 31;
        for (int e = warp; e < TILE; e += 8) {
            const float* row = g_a + (size_t)(r0 + e) * DD;
            float v[4], s = 0.f, s2 = 0.f;
#pragma unroll
            for (int j = 0; j < 4; j++) {
                v[j] = row[lane + 32 * j];
                s += v[j];
                s2 += v[j] * v[j];
            }
#pragma unroll
            for (int o = 16; o > 0; o >>= 1) {
                s += __shfl_xor_sync(0xffffffffu, s, o);
                s2 += __shfl_xor_sync(0xffffffffu, s2, o);
            }
            const float mu = s * (1.f / 128.f);
            const float var = s2 * (1.f / 128.f) - mu * mu;
            const float rstd = rsqrtf(var + GN_EPS);
#pragma unroll
            for (int j = 0; j < 4; j++) {
                const int ch = lane + 32 * j;
                sA[e * STR + ch] = fmaxf((v[j] - mu) * rstd * ng[ch] + nb[ch], 0.f);
            }
        }
    }
    __syncthreads();
    unsigned long long acc[8][4];
    ZACC(acc);
    gemm8x8(lW, DD, DD, sA, sW, acc, g);
    __syncthreads();
    // gn (no relu) + residual + relu -> nxt
    gn_regs<2>(acc, nxt + (size_t)r0 * DD, DD, lg, lb, sRed, g, cur + (size_t)r0 * DD);
}

#define SMEM_ACT ((TILE * STR + 2 * SWBUF + TILE * 4) * 4)
#define SMEM_EDGE ((3 * TILE * STR + 2 * SWBUF + TILE * 4) * 4 + TILE * 4 * 4)

extern "C" void kernel_launch(void* const* d_in, const int* in_sizes, int n_in,
                              void* d_out, int out_size) {
    (void)in_sizes; (void)n_in; (void)out_size;
    const float* actors = (const float*)d_in[0];
    const float* nodes = (const float*)d_in[1];
    const float* actor_ctrs = (const float*)d_in[2];
    const float* node_ctrs = (const float*)d_in[3];
    const int* hi = (const int*)d_in[4];
    const int* wi = (const int*)d_in[5];
    const float* d0W = (const float*)d_in[6];
    const float* d0b = (const float*)d_in[7];
    const float* d1W = (const float*)d_in[8];
    const float* d1g = (const float*)d_in[9];
    const float* d1b = (const float*)d_in[10];
    const float* qW = (const float*)d_in[11];
    const float* qg = (const float*)d_in[12];
    const float* qb = (const float*)d_in[13];
    const float* c0W = (const float*)d_in[14];
    const float* c0g = (const float*)d_in[15];
    const float* c0b = (const float*)d_in[16];
    const float* c1W = (const float*)d_in[17];
    const float* aW = (const float*)d_in[18];
    const float* ng = (const float*)d_in[19];
    const float* nb = (const float*)d_in[20];
    const float* lW = (const float*)d_in[21];
    const float* lg = (const float*)d_in[22];
    const float* lb = (const float*)d_in[23];
    float* out = (float*)d_out;

    cudaFuncSetAttribute(pre_kernel, cudaFuncAttributeMaxDynamicSharedMemorySize, SMEM_ACT);
    cudaFuncSetAttribute(edge_kernel, cudaFuncAttributeMaxDynamicSharedMemorySize, SMEM_EDGE);
    cudaFuncSetAttribute(post_kernel, cudaFuncAttributeMaxDynamicSharedMemorySize, SMEM_ACT);

    for (int blk = 0; blk < 2; blk++) {
        const int off = blk * DD;
        pre_kernel<<<NA / TILE, NTH, SMEM_ACT>>>(actors, qW + blk * DD * DD, qg + off, qb + off,
                                                 aW + blk * DD * DD, blk);
        edge_kernel<<<NE / TILE, NTH, SMEM_EDGE>>>(
            actor_ctrs, node_ctrs, hi, wi, nodes,
            d0W + blk * DD * 2, d0b + off,
            d1W + blk * DD * DD, d1g + off, d1b + off,
            c0W + blk * DD * 3 * DD, c0g + off, c0b + off,
            c1W + blk * DD * DD);
        post_kernel<<<NA / TILE, NTH, SMEM_ACT>>>(actors, ng + off, nb + off, lW + blk * DD * DD,
                                                  lg + off, lb + off, out, blk);
    }
}

// round 8
// speedup vs baseline: 1.4868x; 1.3423x over previous
#include <cuda_runtime.h>

#define NA 8192
#define NN 65536
#define NE 262144
#define DD 128
#define GN_EPS 1e-5f
#define TILE 128
#define STR 132      // activation row stride (floats)
#define NTH 256
#define WCH 16       // weight k-chunk width
#define SWBUF (WCH * 128)

// scratch (device globals: allocation-free rule)
__device__ __align__(16) float g_qc[NA * DD];      // q @ ctx0_Wq^T  per actor
__device__ __align__(16) float g_nc[NN * DD];      // nodes @ ctx0_Wc^T per node
__device__ __align__(16) float g_a[NA * DD];       // agt accumulator
__device__ __align__(16) float g_actors[NA * DD];  // inter-block actors

// ---------- packed f32x2 helpers ----------
__device__ __forceinline__ void ffma2(unsigned long long& acc, unsigned long long w,
                                      unsigned long long a) {
    asm volatile("fma.rn.f32x2 %0, %1, %2, %0;" : "+l"(acc) : "l"(w), "l"(a));
}
__device__ __forceinline__ unsigned long long pack2(float x) {
    unsigned long long r;
    asm("mov.b64 %0, {%1, %1};" : "=l"(r) : "f"(x));
    return r;
}
__device__ __forceinline__ unsigned long long packf2(float lo, float hi) {
    unsigned long long r;
    asm("mov.b64 %0, {%1, %2};" : "=l"(r) : "f"(lo), "f"(hi));
    return r;
}
__device__ __forceinline__ float2 unpack2(unsigned long long v) {
    float2 r;
    asm("mov.b64 {%0, %1}, %2;" : "=f"(r.x), "=f"(r.y) : "l"(v));
    return r;
}
__device__ __forceinline__ void redv4(const float* p, float a, float b, float c, float d) {
    asm volatile("red.global.add.v4.f32 [%0], {%1, %2, %3, %4};"
                 :: "l"(p), "f"(a), "f"(b), "f"(c), "f"(d) : "memory");
}

// thread tile geometry: 8 warps = 4 edge-blocks x 2 oc-blocks
// lane = eg*8 + og ; thread owns edges [eRow0, eRow0+8), ocs [o0, o0+8)
struct TG {
    int t, lane, og, ocblk, eRow0, o0;
};
__device__ __forceinline__ TG tgeom() {
    TG g;
    g.t = threadIdx.x;
    const int warp = g.t >> 5;
    g.lane = g.t & 31;
    g.og = g.lane & 7;
    g.ocblk = warp & 1;
    g.eRow0 = (warp >> 1) * 32 + (g.lane >> 3) * 8;
    g.o0 = g.ocblk * 64 + g.og * 8;
    return g;
}

// ---------- 8x8 register-tile GEMM: acc += Act[128][K=128] * W[128][K]^T ----------
__device__ __forceinline__ void gemm8x8(const float* __restrict__ W, int ldW,
                                        const float* sAct, float* sW,
                                        unsigned long long (&acc)[8][4], const TG& g) {
    const int oc = g.t & 127;
    const int kh = (g.t >> 7) * 8;
    const int nch = DD >> 4;
    float4 w0 = *(const float4*)(W + oc * ldW + kh);
    float4 w1 = *(const float4*)(W + oc * ldW + kh + 4);
    for (int c = 0; c < nch; c++) {
        float* sb = sW + (c & 1) * SWBUF;
        sb[(kh + 0) * 128 + oc] = w0.x;
        sb[(kh + 1) * 128 + oc] = w0.y;
        sb[(kh + 2) * 128 + oc] = w0.z;
        sb[(kh + 3) * 128 + oc] = w0.w;
        sb[(kh + 4) * 128 + oc] = w1.x;
        sb[(kh + 5) * 128 + oc] = w1.y;
        sb[(kh + 6) * 128 + oc] = w1.z;
        sb[(kh + 7) * 128 + oc] = w1.w;
        __syncthreads();
        if (c + 1 < nch) {
            const float* Wp = W + oc * ldW + ((c + 1) << 4) + kh;
            w0 = *(const float4*)(Wp);
            w1 = *(const float4*)(Wp + 4);
        }
        const int k0 = c << 4;
#pragma unroll
        for (int kq = 0; kq < 4; kq++) {
            float4 a4[8];
#pragma unroll
            for (int i = 0; i < 8; i++)
                a4[i] = *(const float4*)(sAct + (g.eRow0 + i) * STR + k0 + kq * 4);
#pragma unroll
            for (int kk = 0; kk < 4; kk++) {
                const int k = kq * 4 + kk;
                const ulonglong2 wa = *(const ulonglong2*)(sb + k * 128 + g.o0);
                const ulonglong2 wb = *(const ulonglong2*)(sb + k * 128 + g.o0 + 4);
#pragma unroll
                for (int i = 0; i < 8; i++) {
                    const float av = (kk == 0) ? a4[i].x : (kk == 1) ? a4[i].y
                                   : (kk == 2) ? a4[i].z : a4[i].w;
                    const unsigned long long aa = pack2(av);
                    ffma2(acc[i][0], wa.x, aa);
                    ffma2(acc[i][1], wa.y, aa);
                    ffma2(acc[i][2], wb.x, aa);
                    ffma2(acc[i][3], wb.y, aa);
                }
            }
        }
    }
}

// ---------- GroupNorm(1 group, 128 ch) from accumulator registers ----------
// MODE 1: store relu(y)    MODE 2: store relu(y + res)
template <int MODE>
__device__ __forceinline__ void gn_regs(const unsigned long long (&acc)[8][4],
                                        float* dst, int dstStride,
                                        const float* __restrict__ gamma,
                                        const float* __restrict__ beta,
                                        float* sRed, const TG& g, const float* res) {
    const float4 g0 = *(const float4*)(gamma + g.o0);
    const float4 g1 = *(const float4*)(gamma + g.o0 + 4);
    const float4 b0 = *(const float4*)(beta + g.o0);
    const float4 b1 = *(const float4*)(beta + g.o0 + 4);
#pragma unroll
    for (int i = 0; i < 8; i++) {
        float s = 0.f, s2 = 0.f;
#pragma unroll
        for (int j = 0; j < 4; j++) {
            float2 p = unpack2(acc[i][j]);
            s += p.x + p.y;
            s2 += p.x * p.x + p.y * p.y;
        }
#pragma unroll
        for (int o = 4; o > 0; o >>= 1) {
            s += __shfl_xor_sync(0xffffffffu, s, o);
            s2 += __shfl_xor_sync(0xffffffffu, s2, o);
        }
        if (g.og == 0) {
            sRed[(g.eRow0 + i) * 4 + g.ocblk * 2 + 0] = s;
            sRed[(g.eRow0 + i) * 4 + g.ocblk * 2 + 1] = s2;
        }
    }
    __syncthreads();
#pragma unroll
    for (int i = 0; i < 8; i++) {
        const int e = g.eRow0 + i;
        const float s = sRed[e * 4 + 0] + sRed[e * 4 + 2];
        const float s2 = sRed[e * 4 + 1] + sRed[e * 4 + 3];
        const float mu = s * (1.f / 128.f);
        const float var = s2 * (1.f / 128.f) - mu * mu;
        const float rstd = rsqrtf(var + GN_EPS);
        float v[8];
#pragma unroll
        for (int j = 0; j < 4; j++) {
            float2 p = unpack2(acc[i][j]);
            v[2 * j] = p.x;
            v[2 * j + 1] = p.y;
        }
        float y[8];
        y[0] = (v[0] - mu) * rstd * g0.x + b0.x;
        y[1] = (v[1] - mu) * rstd * g0.y + b0.y;
        y[2] = (v[2] - mu) * rstd * g0.z + b0.z;
        y[3] = (v[3] - mu) * rstd * g0.w + b0.w;
        y[4] = (v[4] - mu) * rstd * g1.x + b1.x;
        y[5] = (v[5] - mu) * rstd * g1.y + b1.y;
        y[6] = (v[6] - mu) * rstd * g1.z + b1.z;
        y[7] = (v[7] - mu) * rstd * g1.w + b1.w;
        if (MODE == 2) {
            const float4 r0 = *(const float4*)(res + (size_t)e * DD + g.o0);
            const float4 r1 = *(const float4*)(res + (size_t)e * DD + g.o0 + 4);
            y[0] += r0.x; y[1] += r0.y; y[2] += r0.z; y[3] += r0.w;
            y[4] += r1.x; y[5] += r1.y; y[6] += r1.z; y[7] += r1.w;
        }
#pragma unroll
        for (int j = 0; j < 8; j++) y[j] = fmaxf(y[j], 0.f);
        *(float4*)(dst + (size_t)e * dstStride + g.o0) = make_float4(y[0], y[1], y[2], y[3]);
        *(float4*)(dst + (size_t)e * dstStride + g.o0 + 4) = make_float4(y[4], y[5], y[6], y[7]);
    }
}

__device__ __forceinline__ void store_acc_raw(const unsigned long long (&acc)[8][4],
                                              float* dst, int stride, const TG& g) {
#pragma unroll
    for (int i = 0; i < 8; i++) {
        float v[8];
#pragma unroll
        for (int j = 0; j < 4; j++) {
            float2 p = unpack2(acc[i][j]);
            v[2 * j] = p.x;
            v[2 * j + 1] = p.y;
        }
        float* d = dst + (size_t)(g.eRow0 + i) * stride + g.o0;
        *(float4*)(d) = make_float4(v[0], v[1], v[2], v[3]);
        *(float4*)(d + 4) = make_float4(v[4], v[5], v[6], v[7]);
    }
}

#define ZACC(acc)                                          \
    _Pragma("unroll") for (int _i = 0; _i < 8; _i++)       \
        _Pragma("unroll") for (int _j = 0; _j < 4; _j++)   \
            acc[_i][_j] = 0ull;

// ---------- node precompute: g_nc = nodes @ ctx0_Wc^T ----------
__global__ void __launch_bounds__(NTH, 1)
node_kernel(const float* __restrict__ nodes, const float* __restrict__ c0Wc) {
    extern __shared__ float sm[];
    float* sA = sm;
    float* sW = sA + TILE * STR;
    const TG g = tgeom();
    const int r0 = blockIdx.x * TILE;
    for (int idx = g.t; idx < TILE * 32; idx += NTH) {
        int e = idx >> 5, c4 = idx & 31;
        *(float4*)(sA + e * STR + c4 * 4) =
            *(const float4*)(nodes + (size_t)(r0 + e) * DD + c4 * 4);
    }
    __syncthreads();
    unsigned long long acc[8][4];
    ZACC(acc);
    gemm8x8(c0Wc, 3 * DD, sA, sW, acc, g);
    store_acc_raw(acc, g_nc + (size_t)r0 * DD, DD, g);
}

// ---------- actor pre: q=relu(gn(actors@qW^T)); g_qc=q@ctx0_Wq^T; g_a=actors@agtW^T ----------
__global__ void __launch_bounds__(NTH, 1)
pre_kernel(const float* __restrict__ actors_in, const float* __restrict__ qW,
           const float* __restrict__ qg, const float* __restrict__ qb,
           const float* __restrict__ c0Wq, const float* __restrict__ aW, int blk) {
    extern __shared__ float sm[];
    float* sA = sm;                   // [128][132]
    float* sQ = sA + TILE * STR;      // [128][132]
    float* sW = sQ + TILE * STR;      // 2 x [16][128]
    float* sRed = sW + 2 * SWBUF;     // [128][4]
    const float* cur = blk ? g_actors : actors_in;
    const TG g = tgeom();
    const int r0 = blockIdx.x * TILE;
    for (int idx = g.t; idx < TILE * 32; idx += NTH) {
        int e = idx >> 5, c4 = idx & 31;
        *(float4*)(sA + e * STR + c4 * 4) =
            *(const float4*)(cur + (size_t)(r0 + e) * DD + c4 * 4);
    }
    __syncthreads();
    unsigned long long acc[8][4];
    ZACC(acc);
    gemm8x8(qW, DD, sA, sW, acc, g);
    gn_regs<1>(acc, sQ, STR, qg, qb, sRed, g, nullptr);
    ZACC(acc);
    gemm8x8(c0Wq, 3 * DD, sQ, sW, acc, g);   // chunk-0 sync orders sQ writes
    store_acc_raw(acc, g_qc + (size_t)r0 * DD, DD, g);
    ZACC(acc);
    gemm8x8(aW, DD, sA, sW, acc, g);
    store_acc_raw(acc, g_a + (size_t)r0 * DD, DD, g);
}

// ---------- fused edge pipeline (3 GEMM units) ----------
__global__ void __launch_bounds__(NTH, 1)
edge_kernel(const float* __restrict__ actor_ctrs, const float* __restrict__ node_ctrs,
            const int* __restrict__ hi, const int* __restrict__ wi,
            const float* __restrict__ d0W, const float* __restrict__ d0b,
            const float* __restrict__ d1W, const float* __restrict__ d1g,
            const float* __restrict__ d1b,
            const float* __restrict__ c0Wd, const float* __restrict__ c0g,
            const float* __restrict__ c0b, const float* __restrict__ c1W) {
    extern __shared__ float sm[];
    float* sD = sm;                   // [128][132]: H1 -> gn(dist1) -> gn(ctx0)
    float* sM = sD + TILE * STR;      // [128][132]: qc[hi]+nc[wi]
    float* sW = sM + TILE * STR;      // 2 x [16][128]
    float* sRed = sW + 2 * SWBUF;     // [128][4]
    int* shi = (int*)(sRed + TILE * 4);
    int* swi = shi + TILE;
    float* sdx = (float*)(swi + TILE);
    float* sdy = sdx + TILE;

    const TG g = tgeom();
    const int t = g.t;
    const int e0 = blockIdx.x * TILE;
    if (t < TILE) {
        int h = hi[e0 + t], w = wi[e0 + t];
        shi[t] = h;
        swi[t] = w;
        sdx[t] = actor_ctrs[2 * h] - node_ctrs[2 * w];
        sdy[t] = actor_ctrs[2 * h + 1] - node_ctrs[2 * w + 1];
    }
    __syncthreads();
    // gather precomputed ctx0 q+c contributions (L2-resident)
#pragma unroll 4
    for (int idx = t; idx < TILE * 32; idx += NTH) {
        int e = idx >> 5, c4 = idx & 31;
        const float4 a = *(const float4*)(g_qc + (size_t)shi[e] * DD + c4 * 4);
        const float4 b = *(const float4*)(g_nc + (size_t)swi[e] * DD + c4 * 4);
        *(float4*)(sM + e * STR + c4 * 4) =
            make_float4(a.x + b.x, a.y + b.y, a.z + b.z, a.w + b.w);
    }
    // H1 = relu(dist0(dvec)) -> sD
    for (int idx = t; idx < TILE * DD; idx += NTH) {
        int e = idx >> 7, ch = idx & 127;
        float v = fmaf(d0W[2 * ch], sdx[e], fmaf(d0W[2 * ch + 1], sdy[e], d0b[ch]));
        sD[e * STR + ch] = fmaxf(v, 0.f);
    }
    __syncthreads();

    unsigned long long acc[8][4];
    // d = relu(gn(H1 @ dist1^T)) -> sD
    ZACC(acc);
    gemm8x8(d1W, DD, sD, sW, acc, g);
    gn_regs<1>(acc, sD, STR, d1g, d1b, sRed, g, nullptr);
    // ctx0: acc = qc[hi]+nc[wi] (from sM) + d @ c0Wd^T; then gn-relu -> sD
#pragma unroll
    for (int i = 0; i < 8; i++) {
        const float* m = sM + (g.eRow0 + i) * STR + g.o0;
        const float4 u0 = *(const float4*)(m);
        const float4 u1 = *(const float4*)(m + 4);
        acc[i][0] = packf2(u0.x, u0.y);
        acc[i][1] = packf2(u0.z, u0.w);
        acc[i][2] = packf2(u1.x, u1.y);
        acc[i][3] = packf2(u1.z, u1.w);
    }
    gemm8x8(c0Wd, 3 * DD, sD, sW, acc, g);   // chunk-0 sync orders sD writes
    gn_regs<1>(acc, sD, STR, c0g, c0b, sRed, g, nullptr);
    // ctx1 -> scatter-add from registers
    ZACC(acc);
    gemm8x8(c1W, DD, sD, sW, acc, g);
#pragma unroll
    for (int i = 0; i < 8; i++) {
        float v[8];
#pragma unroll
        for (int j = 0; j < 4; j++) {
            float2 p = unpack2(acc[i][j]);
            v[2 * j] = p.x;
            v[2 * j + 1] = p.y;
        }
        const float* p = g_a + (size_t)shi[g.eRow0 + i] * DD + g.o0;
        redv4(p, v[0], v[1], v[2], v[3]);
        redv4(p + 4, v[4], v[5], v[6], v[7]);
    }
}

// ---------- actor post: a=relu(gn(a)); a=gn(a@linW^T); out=relu(a+res) ----------
__global__ void __launch_bounds__(NTH, 1)
post_kernel(const float* __restrict__ actors_in, const float* __restrict__ ng,
            const float* __restrict__ nb, const float* __restrict__ lW,
            const float* __restrict__ lg, const float* __restrict__ lb,
            float* __restrict__ out, int blk) {
    extern __shared__ float sm[];
    float* sA = sm;
    float* sW = sA + TILE * STR;
    float* sRed = sW + 2 * SWBUF;
    const float* cur = blk ? g_actors : actors_in;
    float* nxt = blk ? out : g_actors;
    const TG g = tgeom();
    const int t = g.t;
    const int r0 = blockIdx.x * TILE;
    {
        const int warp = t >> 5, lane = t & 31;
        for (int e = warp; e < TILE; e += 8) {
            const float* row = g_a + (size_t)(r0 + e) * DD;
            float v[4], s = 0.f, s2 = 0.f;
#pragma unroll
            for (int j = 0; j < 4; j++) {
                v[j] = row[lane + 32 * j];
                s += v[j];
                s2 += v[j] * v[j];
            }
#pragma unroll
            for (int o = 16; o > 0; o >>= 1) {
                s += __shfl_xor_sync(0xffffffffu, s, o);
                s2 += __shfl_xor_sync(0xffffffffu, s2, o);
            }
            const float mu = s * (1.f / 128.f);
            const float var = s2 * (1.f / 128.f) - mu * mu;
            const float rstd = rsqrtf(var + GN_EPS);
#pragma unroll
            for (int j = 0; j < 4; j++) {
                const int ch = lane + 32 * j;
                sA[e * STR + ch] = fmaxf((v[j] - mu) * rstd * ng[ch] + nb[ch], 0.f);
            }
        }
    }
    __syncthreads();
    unsigned long long acc[8][4];
    ZACC(acc);
    gemm8x8(lW, DD, sA, sW, acc, g);
    gn_regs<2>(acc, nxt + (size_t)r0 * DD, DD, lg, lb, sRed, g, cur + (size_t)r0 * DD);
}

#define SMEM_PRE ((2 * TILE * STR + 2 * SWBUF + TILE * 4) * 4)
#define SMEM_NODE ((TILE * STR + 2 * SWBUF) * 4)
#define SMEM_EDGE ((2 * TILE * STR + 2 * SWBUF + TILE * 4) * 4 + TILE * 4 * 4)
#define SMEM_POST ((TILE * STR + 2 * SWBUF + TILE * 4) * 4)

extern "C" void kernel_launch(void* const* d_in, const int* in_sizes, int n_in,
                              void* d_out, int out_size) {
    (void)in_sizes; (void)n_in; (void)out_size;
    const float* actors = (const float*)d_in[0];
    const float* nodes = (const float*)d_in[1];
    const float* actor_ctrs = (const float*)d_in[2];
    const float* node_ctrs = (const float*)d_in[3];
    const int* hi = (const int*)d_in[4];
    const int* wi = (const int*)d_in[5];
    const float* d0W = (const float*)d_in[6];
    const float* d0b = (const float*)d_in[7];
    const float* d1W = (const float*)d_in[8];
    const float* d1g = (const float*)d_in[9];
    const float* d1b = (const float*)d_in[10];
    const float* qW = (const float*)d_in[11];
    const float* qg = (const float*)d_in[12];
    const float* qb = (const float*)d_in[13];
    const float* c0W = (const float*)d_in[14];
    const float* c0g = (const float*)d_in[15];
    const float* c0b = (const float*)d_in[16];
    const float* c1W = (const float*)d_in[17];
    const float* aW = (const float*)d_in[18];
    const float* ng = (const float*)d_in[19];
    const float* nb = (const float*)d_in[20];
    const float* lW = (const float*)d_in[21];
    const float* lg = (const float*)d_in[22];
    const float* lb = (const float*)d_in[23];
    float* out = (float*)d_out;

    cudaFuncSetAttribute(pre_kernel, cudaFuncAttributeMaxDynamicSharedMemorySize, SMEM_PRE);
    cudaFuncSetAttribute(node_kernel, cudaFuncAttributeMaxDynamicSharedMemorySize, SMEM_NODE);
    cudaFuncSetAttribute(edge_kernel, cudaFuncAttributeMaxDynamicSharedMemorySize, SMEM_EDGE);
    cudaFuncSetAttribute(post_kernel, cudaFuncAttributeMaxDynamicSharedMemorySize, SMEM_POST);

    for (int blk = 0; blk < 2; blk++) {
        const int off = blk * DD;
        const float* c0Wb = c0W + (size_t)blk * DD * 3 * DD;
        node_kernel<<<NN / TILE, NTH, SMEM_NODE>>>(nodes, c0Wb + 2 * DD);
        pre_kernel<<<NA / TILE, NTH, SMEM_PRE>>>(actors, qW + blk * DD * DD, qg + off, qb + off,
                                                 c0Wb + DD, aW + blk * DD * DD, blk);
        edge_kernel<<<NE / TILE, NTH, SMEM_EDGE>>>(
            actor_ctrs, node_ctrs, hi, wi,
            d0W + blk * DD * 2, d0b + off,
            d1W + blk * DD * DD, d1g + off, d1b + off,
            c0Wb, c0g + off, c0b + off,
            c1W + blk * DD * DD);
        post_kernel<<<NA / TILE, NTH, SMEM_POST>>>(actors, ng + off, nb + off, lW + blk * DD * DD,
                                                   lg + off, lb + off, out, blk);
    }
}